// round 14
// baseline (speedup 1.0000x reference)
#include <cuda_runtime.h>
#include <cuda_bf16.h>

// SuctionNet two-phase:
//   Phase 1: scores[v] = (w0.feats[v]+b0, w1.feats[v]+b1) for all voxels,
//            streaming the 153.6MB table sequentially.
//            16 lanes per voxel: lane m owns channels {4m.., 64+4m.., 128+4m..,
//            192+4m..}; half-warps process adjacent voxels. 2.5 shuffles/voxel,
//            8 independent LDG.128 in flight (4 rows/iter).
//   Phase 2: out[p] = scores[idx[p]], 4 points/thread (int4 idx, float4 stores),
//            gathers hit the 1.2MB L2-resident score table.

#define FEAT_DIM 256
#define N_VOXELS_MAX 150016
#define FULL 0xFFFFFFFFu

__device__ float2 g_scores[N_VOXELS_MAX];

__device__ __forceinline__ float dot4(const float4 a, const float4 w) {
    float s = a.x * w.x;
    s = fmaf(a.y, w.y, s);
    s = fmaf(a.z, w.z, s);
    s = fmaf(a.w, w.w, s);
    return s;
}

__global__ __launch_bounds__(128)
void score_voxels(const float* __restrict__ feats,
                  const float* __restrict__ w,
                  const float* __restrict__ bias,
                  int nv)
{
    const int lane = threadIdx.x & 31;
    const int m    = lane & 15;          // sublane within 16-lane group
    const int h    = lane >> 4;          // group: 0 or 1
    const int warp = (blockIdx.x * blockDim.x + threadIdx.x) >> 5;
    const int base = warp * 32;          // this warp's 32 voxels
    if (base >= nv) return;

    // Weight slice for lane m: float4 indices {m, 16+m, 32+m, 48+m}.
    const float4* w0f = reinterpret_cast<const float4*>(w);
    const float4* w1f = reinterpret_cast<const float4*>(w + FEAT_DIM);
    float4 w0[4], w1[4];
    #pragma unroll
    for (int i = 0; i < 4; i++) {
        w0[i] = __ldg(w0f + 16 * i + m);
        w1[i] = __ldg(w1f + 16 * i + m);
    }
    const float bsel = (m < 8) ? __ldg(bias) : __ldg(bias + 1);

    #pragma unroll
    for (int j0 = 0; j0 < 32; j0 += 4) {
        const int vA = base + j0 + h;         // pair A: adjacent rows
        const int vB = base + j0 + 2 + h;     // pair B
        const float4* rA = reinterpret_cast<const float4*>(
            feats + (size_t)(vA < nv ? vA : 0) * FEAT_DIM);
        const float4* rB = reinterpret_cast<const float4*>(
            feats + (size_t)(vB < nv ? vB : 0) * FEAT_DIM);

        // 8 independent LDG.128 (each instr: two contiguous 256B segments).
        const float4 a0 = __ldg(rA + m);
        const float4 a1 = __ldg(rA + 16 + m);
        const float4 a2 = __ldg(rA + 32 + m);
        const float4 a3 = __ldg(rA + 48 + m);
        const float4 c0 = __ldg(rB + m);
        const float4 c1 = __ldg(rB + 16 + m);
        const float4 c2 = __ldg(rB + 32 + m);
        const float4 c3 = __ldg(rB + 48 + m);

        // ---- pair A ----
        {
            float s0 = dot4(a0, w0[0]) + dot4(a1, w0[1]) + dot4(a2, w0[2]) + dot4(a3, w0[3]);
            float s1 = dot4(a0, w1[0]) + dot4(a1, w1[1]) + dot4(a2, w1[2]) + dot4(a3, w1[3]);
            const float t0 = __shfl_xor_sync(FULL, s0, 8);
            const float t1 = __shfl_xor_sync(FULL, s1, 8);
            float acc = (m < 8) ? (s0 + t0) : (s1 + t1);
            acc += __shfl_xor_sync(FULL, acc, 4);
            acc += __shfl_xor_sync(FULL, acc, 2);
            acc += __shfl_xor_sync(FULL, acc, 1);
            if (vA < nv) {
                if (m == 0) g_scores[vA].x = acc + bsel;   // lanes 0,16
                if (m == 8) g_scores[vA].y = acc + bsel;   // lanes 8,24
            }
        }
        // ---- pair B ----
        {
            float s0 = dot4(c0, w0[0]) + dot4(c1, w0[1]) + dot4(c2, w0[2]) + dot4(c3, w0[3]);
            float s1 = dot4(c0, w1[0]) + dot4(c1, w1[1]) + dot4(c2, w1[2]) + dot4(c3, w1[3]);
            const float t0 = __shfl_xor_sync(FULL, s0, 8);
            const float t1 = __shfl_xor_sync(FULL, s1, 8);
            float acc = (m < 8) ? (s0 + t0) : (s1 + t1);
            acc += __shfl_xor_sync(FULL, acc, 4);
            acc += __shfl_xor_sync(FULL, acc, 2);
            acc += __shfl_xor_sync(FULL, acc, 1);
            if (vB < nv) {
                if (m == 0) g_scores[vB].x = acc + bsel;
                if (m == 8) g_scores[vB].y = acc + bsel;
            }
        }
    }
}

__global__ __launch_bounds__(256)
void scatter_scores(const int* __restrict__ idx,
                    float* __restrict__ out,
                    int n)
{
    const int t = blockIdx.x * blockDim.x + threadIdx.x;
    const int p = t * 4;
    if (p + 3 < n) {
        const int4 v = __ldg(reinterpret_cast<const int4*>(idx) + t);
        const float2 s0 = g_scores[v.x];   // 4 independent L2 gathers
        const float2 s1 = g_scores[v.y];
        const float2 s2 = g_scores[v.z];
        const float2 s3 = g_scores[v.w];
        *reinterpret_cast<float4*>(out + p)     = make_float4(s0.x, s1.x, s2.x, s3.x);
        *reinterpret_cast<float4*>(out + n + p) = make_float4(s0.y, s1.y, s2.y, s3.y);
    } else {
        for (int q = p; q < n; q++) {
            const float2 s = g_scores[__ldg(idx + q)];
            out[q]     = s.x;
            out[n + q] = s.y;
        }
    }
}

extern "C" void kernel_launch(void* const* d_in, const int* in_sizes, int n_in,
                              void* d_out, int out_size)
{
    const float* feats = (const float*)d_in[0];      // [150000*256]
    const int*   idx   = (const int*)d_in[1];        // [200000] int32
    const float* w     = (const float*)d_in[2];      // [2*256]
    const float* b     = (const float*)d_in[3];      // [2]
    float* out = (float*)d_out;                      // [2 * n]

    const int nv = in_sizes[0] / FEAT_DIM;           // 150000 voxels
    const int n  = in_sizes[1];                      // 200000 points

    // Phase 1: score every voxel (streaming).
    const int warps1  = (nv + 31) / 32;              // 4688
    const int blocks1 = (warps1 + 3) / 4;            // 1172
    score_voxels<<<blocks1, 128>>>(feats, w, b, nv);

    // Phase 2: 4 points per thread.
    const int threads2 = 256;
    const int blocks2  = (n / 4 + threads2 - 1) / threads2;   // 196
    scatter_scores<<<blocks2, threads2>>>(idx, out, n);
}